// round 14
// baseline (speedup 1.0000x reference)
#include <cuda_runtime.h>
#include <cstdint>

// RVQ — mma.sync tf32 approx GEMM + exact-fp32 refine.
// Single-barrier-per-chunk mainloop: per-chunk min cells (epoch-sealed),
// register prefix-min threshold => deterministic candidate set.
// embeddings: [16, 128, 64, 64] f32 (d_in[0])
// codebooks : [8, 1024, 128]  f32  (d_in[1])
// out       : [16, 128, 64, 64] f32

#define NBOOK   8
#define KCB     1024
#define EDIM    128
#define NROWS   65536
#define TPB     512
#define CHUNK   128
#define NCHUNK  (KCB / CHUNK)
#define EPSM    1e-3f
#define CANDMAX 16
#define PA      132
#define PB      132

// float-index smem offsets
#define OFF_A     0
#define OFF_B0    (OFF_A + 128 * PA)       // also: final quant tile
#define OFF_B1    (OFF_B0 + CHUNK * PB)    // also: transpose scratch
#define OFF_NORM  (OFF_B1 + CHUNK * PB)
#define OFF_SA    (OFF_NORM + KCB)
#define OFF_CELLS (OFF_SA + 128)           // [8][128] per-chunk min cells
#define OFF_CNT   (OFF_CELLS + NCHUNK * 128)
#define OFF_BEST8 (OFF_CNT + 128)          // [8][128] ints
#define OFF_CAND  (OFF_BEST8 + 8 * 128)
#define SM_FLOATS (OFF_CAND + 128 * CANDMAX)

__device__ float g_norms[NBOOK * KCB];

__device__ __forceinline__ uint32_t smem_u32(const void* p) {
    uint32_t a;
    asm("{ .reg .u64 t; cvta.to.shared.u64 t, %1; cvt.u32.u64 %0, t; }"
        : "=r"(a) : "l"(p));
    return a;
}
__device__ __forceinline__ void cp_async16(uint32_t dst, const void* src) {
    asm volatile("cp.async.cg.shared.global [%0], [%1], 16;"
                 :: "r"(dst), "l"(src) : "memory");
}
#define MMA_TF32(d, a, b0, b1)                                          \
    asm volatile(                                                        \
        "mma.sync.aligned.m16n8k8.row.col.f32.tf32.tf32.f32 "           \
        "{%0,%1,%2,%3}, {%4,%5,%6,%7}, {%8,%9}, {%0,%1,%2,%3};"         \
        : "+f"((d)[0]), "+f"((d)[1]), "+f"((d)[2]), "+f"((d)[3])         \
        : "r"((a)[0]), "r"((a)[1]), "r"((a)[2]), "r"((a)[3]),            \
          "r"(b0), "r"(b1))

// ---------------------------------------------------------------------------
// norms: C_k = sum_e fl(c*c), e ascending (exact chain); float4 loads
// ---------------------------------------------------------------------------
__global__ void k_norms(const float* __restrict__ cb) {
    int idx = blockIdx.x * 64 + threadIdx.x;
    if (idx >= NBOOK * KCB) return;
    const float4* c4 = (const float4*)(cb + (size_t)idx * EDIM);
    float acc = 0.0f;
#pragma unroll 8
    for (int e = 0; e < EDIM / 4; e++) {
        float4 v = __ldg(c4 + e);
        acc = __fadd_rn(acc, __fmul_rn(v.x, v.x));
        acc = __fadd_rn(acc, __fmul_rn(v.y, v.y));
        acc = __fadd_rn(acc, __fmul_rn(v.z, v.z));
        acc = __fadd_rn(acc, __fmul_rn(v.w, v.w));
    }
    g_norms[idx] = acc;
}

// ---------------------------------------------------------------------------
// fused RVQ: one CTA = 128 rows through all 8 books. 512 threads (16 warps).
// Warp grid 4M x 4N; warp tile 32 rows x 32 codes.
// ---------------------------------------------------------------------------
__global__ void __launch_bounds__(TPB, 1)
k_rvq(const float* __restrict__ emb, const float* __restrict__ cb,
      float* __restrict__ out) {
    extern __shared__ float smf[];
    const uint32_t sb = smem_u32(smf);
    const int t = threadIdx.x, lane = t & 31, w = t >> 5;
    const int wm = w & 3, wn = w >> 2;     // 4 M-warps x 4 N-warps
    const int blk = blockIdx.x;
    const int b = blk >> 5;                // batch
    const int hw0 = (blk & 31) << 7;       // hw offset

    float* A     = smf + OFF_A;
    float* sNorm = smf + OFF_NORM;
    float* sA    = smf + OFF_SA;
    unsigned* cellsU = (unsigned*)(smf + OFF_CELLS);
    int*   cnt    = (int*)(smf + OFF_CNT);
    int*   sBest8 = (int*)(smf + OFF_BEST8);
    int*   candk  = (int*)(smf + OFF_CAND);

    // load residual tile (exact): A[i][e] = emb[b][e][hw0+i]
    for (int v = t; v < 128 * 128; v += TPB) {
        int e = v >> 7, i = v & 127;
        A[i * PA + e] = emb[((size_t)(b * 128 + e) << 12) + hw0 + i];
    }
    // stage book0/chunk0 into B0 (waited at first book-start barrier)
    for (int v = t; v < CHUNK * 32; v += TPB) {
        int code = v >> 5, s = v & 31;
        cp_async16(sb + (OFF_B0 + code * PB + s * 4) * 4,
                   cb + (size_t)code * EDIM + s * 4);
    }
    asm volatile("cp.async.commit_group;" ::: "memory");
    __syncthreads();   // A tile stable (for sA below)

    const int frow = lane >> 2;            // 0..7
    const int fcol = lane & 3;             // 0..3

    for (int book = 0; book < NBOOK; book++) {
        const float* cbg = cb + (size_t)book * KCB * EDIM;

        // book-start phase: norms, reset cells/cnt, exact A-norms
        for (int v = t; v < KCB; v += TPB) sNorm[v] = g_norms[book * KCB + v];
        for (int v = t; v < NCHUNK * 128; v += TPB) cellsU[v] = 0x7f7fffffu;
        if (t < 128) {
            cnt[t] = 0;
            // A = ||r||^2 exact chain (e ascending, fl(mul) then fl(add))
            float acc = 0.0f;
            const float* ar = &A[t * PA];
            for (int e = 0; e < EDIM; e++)
                acc = __fadd_rn(acc, __fmul_rn(ar[e], ar[e]));
            sA[t] = acc;
        }
        asm volatile("cp.async.wait_group 0;" ::: "memory");  // chunk0 staged
        __syncthreads();

        float arg[2][2], premin[2][2];
#pragma unroll
        for (int mt = 0; mt < 2; mt++)
#pragma unroll
            for (int h = 0; h < 2; h++) {
                arg[mt][h] = sA[wm * 32 + mt * 16 + frow + h * 8];
                premin[mt][h] = 3.4e38f;
            }

        for (int c = 0; c < NCHUNK; c++) {
            const float* Bc = smf + ((c & 1) ? OFF_B1 : OFF_B0);

            // issue prefetch of next chunk (or next book's chunk 0).
            // Safe: all warps passed the previous barrier, which followed
            // their MMA on the buffer being overwritten.
            bool has_next = !(book == NBOOK - 1 && c == NCHUNK - 1);
            if (has_next) {
                const float* srcn = (c + 1 < NCHUNK)
                    ? cbg + (size_t)(c + 1) * CHUNK * EDIM
                    : cbg + (size_t)KCB * EDIM;   // next book chunk 0
                int nboff = ((c + 1) & 1) ? OFF_B1 : OFF_B0;
                for (int v = t; v < CHUNK * 32; v += TPB) {
                    int code = v >> 5, s = v & 31;
                    cp_async16(sb + (nboff + code * PB + s * 4) * 4,
                               srcn + (size_t)code * EDIM + s * 4);
                }
                asm volatile("cp.async.commit_group;" ::: "memory");
            }

            // ---- tf32 MMA (truncated fp32 inputs): 2 m16 x 4 n8 x 16 k8 ----
            float d[2][4][4];
#pragma unroll
            for (int mt = 0; mt < 2; mt++)
#pragma unroll
                for (int nt = 0; nt < 4; nt++)
#pragma unroll
                    for (int q = 0; q < 4; q++) d[mt][nt][q] = 0.0f;

#pragma unroll 4
            for (int ks = 0; ks < 16; ks++) {
                int k0 = ks * 8;
                uint32_t a[2][4];
#pragma unroll
                for (int mt = 0; mt < 2; mt++) {
                    int r0 = wm * 32 + mt * 16 + frow;
                    a[mt][0] = __float_as_uint(A[r0 * PA + k0 + fcol]);
                    a[mt][1] = __float_as_uint(A[(r0 + 8) * PA + k0 + fcol]);
                    a[mt][2] = __float_as_uint(A[r0 * PA + k0 + fcol + 4]);
                    a[mt][3] = __float_as_uint(A[(r0 + 8) * PA + k0 + fcol + 4]);
                }
#pragma unroll
                for (int nt = 0; nt < 4; nt++) {
                    int cl = wn * 32 + nt * 8 + frow;
                    uint32_t b0 = __float_as_uint(Bc[cl * PB + k0 + fcol]);
                    uint32_t b1 = __float_as_uint(Bc[cl * PB + k0 + fcol + 4]);
                    MMA_TF32(d[0][nt], a[0], b0, b1);
                    MMA_TF32(d[1][nt], a[1], b0, b1);
                }
            }

            // ---- epilogue: d_app = fma(-2,S,A) + C ----
            int kchunk = c * CHUNK + wn * 32;
#pragma unroll
            for (int mt = 0; mt < 2; mt++)
#pragma unroll
                for (int nt = 0; nt < 4; nt++)
#pragma unroll
                    for (int q = 0; q < 4; q++) {
                        int k = kchunk + nt * 8 + 2 * fcol + (q & 1);
                        d[mt][nt][q] = __fadd_rn(
                            __fmaf_rn(-2.0f, d[mt][nt][q], arg[mt][q >> 1]),
                            sNorm[k]);
                    }

            // ---- collect(c>0) with prefix(c-1) from SEALED cells ----
            // cells[c-1] was last written in epoch c-1 (sealed by the
            // previous barrier) => threshold deterministic. Superset of the
            // final-prefix window since prefix-min only decreases.
            if (c > 0) {
#pragma unroll
                for (int mt = 0; mt < 2; mt++)
#pragma unroll
                    for (int h = 0; h < 2; h++) {
                        int row = wm * 32 + mt * 16 + frow + h * 8;
                        float pm = fminf(premin[mt][h],
                            __uint_as_float(cellsU[(c - 1) * 128 + row]));
                        premin[mt][h] = pm;
                        float thr = pm + EPSM;
#pragma unroll
                        for (int nt = 0; nt < 4; nt++)
#pragma unroll
                            for (int qq = 0; qq < 2; qq++) {
                                if (d[mt][nt][h * 2 + qq] <= thr) {
                                    int k = kchunk + nt * 8 + 2 * fcol + qq;
                                    int p = atomicAdd(&cnt[row], 1);
                                    if (p < CANDMAX)
                                        candk[row * CANDMAX + p] = k;
                                }
                            }
                    }
            }

            // ---- per-chunk min into cells[c] (this epoch's cell only) ----
#pragma unroll
            for (int mt = 0; mt < 2; mt++)
#pragma unroll
                for (int h = 0; h < 2; h++) {
                    float lm = 3.4e38f;
#pragma unroll
                    for (int nt = 0; nt < 4; nt++)
                        lm = fminf(lm, fminf(d[mt][nt][h * 2],
                                             d[mt][nt][h * 2 + 1]));
                    int row = wm * 32 + mt * 16 + frow + h * 8;
                    atomicMin(&cellsU[c * 128 + row], __float_as_uint(lm));
                }

            asm volatile("cp.async.wait_group 0;" ::: "memory");
            __syncthreads();   // seals cells[c]; publishes prefetched buffer

            // ---- chunk 0: collect after its barrier from sealed cell 0 ----
            if (c == 0) {
#pragma unroll
                for (int mt = 0; mt < 2; mt++)
#pragma unroll
                    for (int h = 0; h < 2; h++) {
                        int row = wm * 32 + mt * 16 + frow + h * 8;
                        float pm = __uint_as_float(cellsU[row]);
                        premin[mt][h] = pm;
                        float thr = pm + EPSM;
#pragma unroll
                        for (int nt = 0; nt < 4; nt++)
#pragma unroll
                            for (int qq = 0; qq < 2; qq++) {
                                if (d[mt][nt][h * 2 + qq] <= thr) {
                                    int k = kchunk + nt * 8 + 2 * fcol + qq;
                                    int p = atomicAdd(&cnt[row], 1);
                                    if (p < CANDMAX)
                                        candk[row * CANDMAX + p] = k;
                                }
                            }
                    }
            }
        }
        // all collects done (chunk 7 collected pre-barrier; cnt/candk stable)

        // ---- exact refine: thread t owns row t (chains identical to R1) ----
        if (t < 128) {
            int n = cnt[t];
            float Arow = sA[t];
            float bd = 3.4e38f; int bk = 0x7fffffff;
            const float* ar = &A[t * PA];
            if (n <= CANDMAX) {
                for (int i = 0; i < n; i++) {
                    int k = candk[t * CANDMAX + i];
                    const float* cp = cbg + (size_t)k * EDIM;
                    float dot = 0.0f;
#pragma unroll 8
                    for (int e = 0; e < EDIM; e += 4) {
                        float4 c4 = __ldg((const float4*)(cp + e));
                        dot = __fmaf_rn(ar[e], c4.x, dot);
                        dot = __fmaf_rn(ar[e + 1], c4.y, dot);
                        dot = __fmaf_rn(ar[e + 2], c4.z, dot);
                        dot = __fmaf_rn(ar[e + 3], c4.w, dot);
                    }
                    float dd = __fadd_rn(__fsub_rn(Arow, 2.0f * dot), sNorm[k]);
                    if (dd < bd || (dd == bd && k < bk)) { bd = dd; bk = k; }
                }
            } else {   // safety fallback: exact full scan (deterministic)
                for (int k = 0; k < KCB; k++) {
                    const float* cp = cbg + (size_t)k * EDIM;
                    float dot = 0.0f;
                    for (int e = 0; e < EDIM; e += 4) {
                        float4 c4 = __ldg((const float4*)(cp + e));
                        dot = __fmaf_rn(ar[e], c4.x, dot);
                        dot = __fmaf_rn(ar[e + 1], c4.y, dot);
                        dot = __fmaf_rn(ar[e + 2], c4.z, dot);
                        dot = __fmaf_rn(ar[e + 3], c4.w, dot);
                    }
                    float dd = __fadd_rn(__fsub_rn(Arow, 2.0f * dot), sNorm[k]);
                    if (dd < bd) { bd = dd; bk = k; }
                }
            }
            sBest8[book * 128 + t] = bk;
        }
        __syncthreads();

        // ---- res -= dec (SMEM, exact). Skipped for last book (res dead). ----
        if (book < NBOOK - 1) {
            for (int v = t; v < 128 * 32; v += TPB) {
                int row = v >> 5, e4 = (v & 31) << 2;
                int k = sBest8[book * 128 + row];
                float4 dec = __ldg((const float4*)(cbg + (size_t)k * EDIM + e4));
                float* rp = &A[row * PA + e4];
                rp[0] = __fsub_rn(rp[0], dec.x);
                rp[1] = __fsub_rn(rp[1], dec.y);
                rp[2] = __fsub_rn(rp[2], dec.z);
                rp[3] = __fsub_rn(rp[3], dec.w);
            }
            __syncthreads();
        }
    }
    __syncthreads();

    // ---- quant reconstruction: q = ((dec0+dec1)+...+dec7), exact order ----
    float* Q = smf + OFF_B0;
    for (int v = t; v < 128 * 32; v += TPB) {
        int row = v >> 5, e4 = (v & 31) << 2;
        float4 q = __ldg((const float4*)(
            cb + ((size_t)sBest8[row]) * EDIM + e4));   // book 0
#pragma unroll
        for (int bkk = 1; bkk < NBOOK; bkk++) {
            int k = sBest8[bkk * 128 + row];
            float4 dv = __ldg((const float4*)(
                cb + ((size_t)bkk * KCB + k) * EDIM + e4));
            q.x = __fadd_rn(q.x, dv.x); q.y = __fadd_rn(q.y, dv.y);
            q.z = __fadd_rn(q.z, dv.z); q.w = __fadd_rn(q.w, dv.w);
        }
        *(float4*)&Q[row * PA + e4] = q;
    }
    __syncthreads();

    // ---- output: Q [row][e] (smem) -> out NCHW, warp-tiled transpose ----
    {
        float* ts = smf + OFF_B1 + w * (32 * 33);
        int i0 = (w & 3) * 32, e0 = (w >> 2) * 32;
#pragma unroll 4
        for (int r = 0; r < 32; r++)
            ts[r * 33 + lane] = Q[(i0 + r) * PA + e0 + lane];
        __syncwarp();
#pragma unroll 4
        for (int r = 0; r < 32; r++)
            out[((size_t)(b * 128 + e0 + r) << 12) + hw0 + i0 + lane] =
                ts[lane * 33 + r];
    }
}

// ---------------------------------------------------------------------------
extern "C" void kernel_launch(void* const* d_in, const int* in_sizes, int n_in,
                              void* d_out, int out_size) {
    (void)in_sizes; (void)n_in; (void)out_size;
    const float* emb = (const float*)d_in[0];
    const float* cb  = (const float*)d_in[1];
    float* out = (float*)d_out;

    const int smem_bytes = SM_FLOATS * 4;
    cudaFuncSetAttribute(k_rvq, cudaFuncAttributeMaxDynamicSharedMemorySize,
                         smem_bytes);
    k_norms<<<NBOOK * KCB / 64, 64>>>(cb);
    k_rvq<<<NROWS / 128, TPB, smem_bytes>>>(emb, cb, out);
}

// round 15
// speedup vs baseline: 3.2958x; 3.2958x over previous
#include <cuda_runtime.h>
#include <cstdint>

// RVQ — mma.sync tf32 approx GEMM + exact-fp32 refine.
// R13 threshold semantics (frozen), retiled to 64 rows x 64-code chunks
// => 111.75KB smem/CTA => 2 CTAs/SM for cross-CTA latency hiding.
// embeddings: [16, 128, 64, 64] f32 (d_in[0])
// codebooks : [8, 1024, 128]  f32  (d_in[1])
// out       : [16, 128, 64, 64] f32

#define NBOOK   8
#define KCB     1024
#define EDIM    128
#define NROWS   65536
#define TPB     256
#define ROWS    64           // rows per CTA
#define CHUNK   64           // codes per chunk
#define NCHUNK  (KCB / CHUNK)   // 16
#define EPSM    1e-3f
#define CANDMAX 24
#define PA      132
#define PB      132

// float-index smem offsets
#define OFF_A     0
#define OFF_B0    (OFF_A + ROWS * PA)      // also: transpose scratch at end
#define OFF_B1    (OFF_B0 + CHUNK * PB)    // also: final quant tile at end
#define OFF_NORM  (OFF_B1 + CHUNK * PB)
#define OFF_SA    (OFF_NORM + KCB)
#define OFF_RMIN  (OFF_SA + ROWS)
#define OFF_CNT   (OFF_RMIN + ROWS)
#define OFF_BEST8 (OFF_CNT + ROWS)         // [8][64] ints
#define OFF_CAND  (OFF_BEST8 + NBOOK * ROWS)
#define SM_FLOATS (OFF_CAND + ROWS * CANDMAX)

__device__ float g_norms[NBOOK * KCB];

__device__ __forceinline__ uint32_t smem_u32(const void* p) {
    uint32_t a;
    asm("{ .reg .u64 t; cvta.to.shared.u64 t, %1; cvt.u32.u64 %0, t; }"
        : "=r"(a) : "l"(p));
    return a;
}
__device__ __forceinline__ void cp_async16(uint32_t dst, const void* src) {
    asm volatile("cp.async.cg.shared.global [%0], [%1], 16;"
                 :: "r"(dst), "l"(src) : "memory");
}
#define MMA_TF32(d, a, b0, b1)                                          \
    asm volatile(                                                        \
        "mma.sync.aligned.m16n8k8.row.col.f32.tf32.tf32.f32 "           \
        "{%0,%1,%2,%3}, {%4,%5,%6,%7}, {%8,%9}, {%0,%1,%2,%3};"         \
        : "+f"((d)[0]), "+f"((d)[1]), "+f"((d)[2]), "+f"((d)[3])         \
        : "r"((a)[0]), "r"((a)[1]), "r"((a)[2]), "r"((a)[3]),            \
          "r"(b0), "r"(b1))

// ---------------------------------------------------------------------------
// norms: C_k = sum_e fl(c*c), e ascending (exact chain); float4 loads
// ---------------------------------------------------------------------------
__global__ void k_norms(const float* __restrict__ cb) {
    int idx = blockIdx.x * 64 + threadIdx.x;
    if (idx >= NBOOK * KCB) return;
    const float4* c4 = (const float4*)(cb + (size_t)idx * EDIM);
    float acc = 0.0f;
#pragma unroll 8
    for (int e = 0; e < EDIM / 4; e++) {
        float4 v = __ldg(c4 + e);
        acc = __fadd_rn(acc, __fmul_rn(v.x, v.x));
        acc = __fadd_rn(acc, __fmul_rn(v.y, v.y));
        acc = __fadd_rn(acc, __fmul_rn(v.z, v.z));
        acc = __fadd_rn(acc, __fmul_rn(v.w, v.w));
    }
    g_norms[idx] = acc;
}

// ---------------------------------------------------------------------------
// fused RVQ: one CTA = 64 rows through all 8 books. 256 threads (8 warps).
// Warp grid 2M x 4N; warp tile 32 rows x 16 codes. 2 CTAs per SM.
// ---------------------------------------------------------------------------
__global__ void __launch_bounds__(TPB, 2)
k_rvq(const float* __restrict__ emb, const float* __restrict__ cb,
      float* __restrict__ out) {
    extern __shared__ float smf[];
    const uint32_t sb = smem_u32(smf);
    const int t = threadIdx.x, lane = t & 31, w = t >> 5;
    const int wm = w & 1, wn = w >> 1;     // 2 M-warps x 4 N-warps
    const int blk = blockIdx.x;
    const int b = blk >> 6;                // batch (64 tiles per batch)
    const int hw0 = (blk & 63) << 6;       // hw offset

    float* A     = smf + OFF_A;
    float* sNorm = smf + OFF_NORM;
    float* sA    = smf + OFF_SA;
    unsigned* rowMinU = (unsigned*)(smf + OFF_RMIN);
    int*   cnt    = (int*)(smf + OFF_CNT);
    int*   sBest8 = (int*)(smf + OFF_BEST8);
    int*   candk  = (int*)(smf + OFF_CAND);

    // load residual tile (exact): A[i][e] = emb[b][e][hw0+i]
    for (int v = t; v < ROWS * EDIM; v += TPB) {
        int e = v >> 6, i = v & (ROWS - 1);
        A[i * PA + e] = emb[((size_t)(b * 128 + e) << 12) + hw0 + i];
    }
    __syncthreads();

    const int frow = lane >> 2;            // 0..7
    const int fcol = lane & 3;             // 0..3

    for (int book = 0; book < NBOOK; book++) {
        const float* cbg = cb + (size_t)book * KCB * EDIM;

        for (int v = t; v < KCB; v += TPB) sNorm[v] = g_norms[book * KCB + v];
        if (t < ROWS) {
            cnt[t] = 0;
            rowMinU[t] = 0x7f7fffffu;
            // A = ||r||^2 exact chain (e ascending, fl(mul) then fl(add))
            float acc = 0.0f;
            const float* ar = &A[t * PA];
            for (int e = 0; e < EDIM; e++)
                acc = __fadd_rn(acc, __fmul_rn(ar[e], ar[e]));
            sA[t] = acc;
        }
        __syncthreads();

        float arg[2][2];
#pragma unroll
        for (int mt = 0; mt < 2; mt++)
#pragma unroll
            for (int h = 0; h < 2; h++)
                arg[mt][h] = sA[wm * 32 + mt * 16 + frow + h * 8];

        // prologue: stage chunk 0 into B0 (per-book, R13 structure)
        for (int v = t; v < CHUNK * 32; v += TPB) {
            int code = v >> 5, s = v & 31;
            cp_async16(sb + (OFF_B0 + code * PB + s * 4) * 4,
                       cbg + (size_t)code * EDIM + s * 4);
        }
        asm volatile("cp.async.commit_group;" ::: "memory");
        asm volatile("cp.async.wait_group 0;" ::: "memory");
        __syncthreads();

        for (int c = 0; c < NCHUNK; c++) {
            const float* Bc = smf + ((c & 1) ? OFF_B1 : OFF_B0);
            if (c + 1 < NCHUNK) {   // prefetch next chunk
                int nboff = ((c + 1) & 1) ? OFF_B1 : OFF_B0;
                const float* srcn = cbg + (size_t)(c + 1) * CHUNK * EDIM;
                for (int v = t; v < CHUNK * 32; v += TPB) {
                    int code = v >> 5, s = v & 31;
                    cp_async16(sb + (nboff + code * PB + s * 4) * 4,
                               srcn + (size_t)code * EDIM + s * 4);
                }
                asm volatile("cp.async.commit_group;" ::: "memory");
            }

            // ---- tf32 MMA (truncated fp32 inputs): 2 m16 x 2 n8 x 16 k8 ----
            float d[2][2][4];
#pragma unroll
            for (int mt = 0; mt < 2; mt++)
#pragma unroll
                for (int nt = 0; nt < 2; nt++)
#pragma unroll
                    for (int q = 0; q < 4; q++) d[mt][nt][q] = 0.0f;

#pragma unroll 4
            for (int ks = 0; ks < 16; ks++) {
                int k0 = ks * 8;
                uint32_t a[2][4];
#pragma unroll
                for (int mt = 0; mt < 2; mt++) {
                    int r0 = wm * 32 + mt * 16 + frow;
                    a[mt][0] = __float_as_uint(A[r0 * PA + k0 + fcol]);
                    a[mt][1] = __float_as_uint(A[(r0 + 8) * PA + k0 + fcol]);
                    a[mt][2] = __float_as_uint(A[r0 * PA + k0 + fcol + 4]);
                    a[mt][3] = __float_as_uint(A[(r0 + 8) * PA + k0 + fcol + 4]);
                }
#pragma unroll
                for (int nt = 0; nt < 2; nt++) {
                    int cl = wn * 16 + nt * 8 + frow;
                    uint32_t b0 = __float_as_uint(Bc[cl * PB + k0 + fcol]);
                    uint32_t b1 = __float_as_uint(Bc[cl * PB + k0 + fcol + 4]);
                    MMA_TF32(d[0][nt], a[0], b0, b1);
                    MMA_TF32(d[1][nt], a[1], b0, b1);
                }
            }

            // ---- epilogue: d_app = fma(-2,S,A) + C; row-min update ----
            int kchunk = c * CHUNK + wn * 16;
#pragma unroll
            for (int mt = 0; mt < 2; mt++)
#pragma unroll
                for (int nt = 0; nt < 2; nt++)
#pragma unroll
                    for (int q = 0; q < 4; q++) {
                        int k = kchunk + nt * 8 + 2 * fcol + (q & 1);
                        d[mt][nt][q] = __fadd_rn(
                            __fmaf_rn(-2.0f, d[mt][nt][q], arg[mt][q >> 1]),
                            sNorm[k]);
                    }
#pragma unroll
            for (int mt = 0; mt < 2; mt++)
#pragma unroll
                for (int h = 0; h < 2; h++) {
                    float lm = fminf(fminf(d[mt][0][h * 2], d[mt][0][h * 2 + 1]),
                                     fminf(d[mt][1][h * 2], d[mt][1][h * 2 + 1]));
                    int row = wm * 32 + mt * 16 + frow + h * 8;
                    atomicMin(&rowMinU[row], __float_as_uint(lm));
                }
            // DETERMINISM barrier: seal prefix-min through chunk c (R13/R8
            // validated semantics — frozen).
            __syncthreads();

            // ---- collect candidates within margin of prefix-min ----
#pragma unroll
            for (int mt = 0; mt < 2; mt++)
#pragma unroll
                for (int h = 0; h < 2; h++) {
                    int row = wm * 32 + mt * 16 + frow + h * 8;
                    float thr = __uint_as_float(rowMinU[row]) + EPSM;
#pragma unroll
                    for (int nt = 0; nt < 2; nt++)
#pragma unroll
                        for (int qq = 0; qq < 2; qq++) {
                            if (d[mt][nt][h * 2 + qq] <= thr) {
                                int k = kchunk + nt * 8 + 2 * fcol + qq;
                                int p = atomicAdd(&cnt[row], 1);
                                if (p < CANDMAX)
                                    candk[row * CANDMAX + p] = k;
                            }
                        }
                }
            if (c + 1 < NCHUNK)
                asm volatile("cp.async.wait_group 0;" ::: "memory");
            __syncthreads();
        }

        // ---- exact refine: thread t owns row t (chains identical to R1) ----
        if (t < ROWS) {
            int n = cnt[t];
            float Arow = sA[t];
            float bd = 3.4e38f; int bk = 0x7fffffff;
            const float* ar = &A[t * PA];
            if (n <= CANDMAX) {
                for (int i = 0; i < n; i++) {
                    int k = candk[t * CANDMAX + i];
                    const float* cp = cbg + (size_t)k * EDIM;
                    float dot = 0.0f;
#pragma unroll 8
                    for (int e = 0; e < EDIM; e += 4) {
                        float4 c4 = __ldg((const float4*)(cp + e));
                        dot = __fmaf_rn(ar[e], c4.x, dot);
                        dot = __fmaf_rn(ar[e + 1], c4.y, dot);
                        dot = __fmaf_rn(ar[e + 2], c4.z, dot);
                        dot = __fmaf_rn(ar[e + 3], c4.w, dot);
                    }
                    float dd = __fadd_rn(__fsub_rn(Arow, 2.0f * dot), sNorm[k]);
                    if (dd < bd || (dd == bd && k < bk)) { bd = dd; bk = k; }
                }
            } else {   // safety fallback: exact full scan (deterministic)
                for (int k = 0; k < KCB; k++) {
                    const float* cp = cbg + (size_t)k * EDIM;
                    float dot = 0.0f;
                    for (int e = 0; e < EDIM; e += 4) {
                        float4 c4 = __ldg((const float4*)(cp + e));
                        dot = __fmaf_rn(ar[e], c4.x, dot);
                        dot = __fmaf_rn(ar[e + 1], c4.y, dot);
                        dot = __fmaf_rn(ar[e + 2], c4.z, dot);
                        dot = __fmaf_rn(ar[e + 3], c4.w, dot);
                    }
                    float dd = __fadd_rn(__fsub_rn(Arow, 2.0f * dot), sNorm[k]);
                    if (dd < bd) { bd = dd; bk = k; }
                }
            }
            sBest8[book * ROWS + t] = bk;
        }
        __syncthreads();

        // ---- res -= dec (SMEM, exact). Skipped for last book (res dead). ----
        if (book < NBOOK - 1) {
            for (int v = t; v < ROWS * 32; v += TPB) {
                int row = v >> 5, e4 = (v & 31) << 2;
                int k = sBest8[book * ROWS + row];
                float4 dec = __ldg((const float4*)(cbg + (size_t)k * EDIM + e4));
                float* rp = &A[row * PA + e4];
                rp[0] = __fsub_rn(rp[0], dec.x);
                rp[1] = __fsub_rn(rp[1], dec.y);
                rp[2] = __fsub_rn(rp[2], dec.z);
                rp[3] = __fsub_rn(rp[3], dec.w);
            }
        }
        __syncthreads();
    }

    // ---- quant reconstruction: q = ((dec0+dec1)+...+dec7), exact order ----
    // Written into the dead B1 region as a [64][PA] tile.
    float* Q = smf + OFF_B1;
    for (int v = t; v < ROWS * 32; v += TPB) {
        int row = v >> 5, e4 = (v & 31) << 2;
        float4 q = __ldg((const float4*)(
            cb + ((size_t)sBest8[row]) * EDIM + e4));   // book 0
#pragma unroll
        for (int bkk = 1; bkk < NBOOK; bkk++) {
            int k = sBest8[bkk * ROWS + row];
            float4 dv = __ldg((const float4*)(
                cb + ((size_t)bkk * KCB + k) * EDIM + e4));
            q.x = __fadd_rn(q.x, dv.x); q.y = __fadd_rn(q.y, dv.y);
            q.z = __fadd_rn(q.z, dv.z); q.w = __fadd_rn(q.w, dv.w);
        }
        *(float4*)&Q[row * PA + e4] = q;
    }
    __syncthreads();

    // ---- output: Q [row][e] (smem) -> out NCHW, warp-tiled transpose ----
    // 8 tiles of 32rows x 32e; one per warp; scratch in dead B0 region.
    {
        float* ts = smf + OFF_B0 + w * (32 * 33);
        int i0 = (w & 1) * 32, e0 = (w >> 1) * 32;
#pragma unroll 4
        for (int r = 0; r < 32; r++)
            ts[r * 33 + lane] = Q[(i0 + r) * PA + e0 + lane];
        __syncwarp();
#pragma unroll 4
        for (int r = 0; r < 32; r++)
            out[((size_t)(b * 128 + e0 + r) << 12) + hw0 + i0 + lane] =
                ts[lane * 33 + r];
    }
}

// ---------------------------------------------------------------------------
extern "C" void kernel_launch(void* const* d_in, const int* in_sizes, int n_in,
                              void* d_out, int out_size) {
    (void)in_sizes; (void)n_in; (void)out_size;
    const float* emb = (const float*)d_in[0];
    const float* cb  = (const float*)d_in[1];
    float* out = (float*)d_out;

    const int smem_bytes = SM_FLOATS * 4;   // ~111.75 KB -> 2 CTAs/SM
    cudaFuncSetAttribute(k_rvq, cudaFuncAttributeMaxDynamicSharedMemorySize,
                         smem_bytes);
    k_norms<<<NBOOK * KCB / 64, 64>>>(cb);
    k_rvq<<<NROWS / ROWS, TPB, smem_bytes>>>(emb, cb, out);
}

// round 16
// speedup vs baseline: 3.6733x; 1.1146x over previous
#include <cuda_runtime.h>
#include <cstdint>

// RVQ — mma.sync tf32 approx GEMM + exact-fp32 refine.
// R13 threshold semantics (prefix-min through own chunk, EPSM=1e-3,
// CANDMAX=16) with R14's per-chunk min cells => ONE barrier per chunk.
// embeddings: [16, 128, 64, 64] f32 (d_in[0])
// codebooks : [8, 1024, 128]  f32  (d_in[1])
// out       : [16, 128, 64, 64] f32

#define NBOOK   8
#define KCB     1024
#define EDIM    128
#define NROWS   65536
#define TPB     512
#define CHUNK   128
#define NCHUNK  (KCB / CHUNK)
#define EPSM    1e-3f
#define CANDMAX 16
#define PA      132
#define PB      132

// float-index smem offsets
#define OFF_A     0
#define OFF_B0    (OFF_A + 128 * PA)       // also: final quant tile
#define OFF_B1    (OFF_B0 + CHUNK * PB)    // also: transpose scratch
#define OFF_NORM  (OFF_B1 + CHUNK * PB)
#define OFF_SA    (OFF_NORM + KCB)
#define OFF_CELLS (OFF_SA + 128)           // [NCHUNK][128] per-chunk min cells
#define OFF_CNT   (OFF_CELLS + NCHUNK * 128)
#define OFF_BEST8 (OFF_CNT + 128)          // [8][128] ints
#define OFF_CAND  (OFF_BEST8 + NBOOK * 128)
#define SM_FLOATS (OFF_CAND + 128 * CANDMAX)

__device__ float g_norms[NBOOK * KCB];

__device__ __forceinline__ uint32_t smem_u32(const void* p) {
    uint32_t a;
    asm("{ .reg .u64 t; cvta.to.shared.u64 t, %1; cvt.u32.u64 %0, t; }"
        : "=r"(a) : "l"(p));
    return a;
}
__device__ __forceinline__ void cp_async16(uint32_t dst, const void* src) {
    asm volatile("cp.async.cg.shared.global [%0], [%1], 16;"
                 :: "r"(dst), "l"(src) : "memory");
}
#define MMA_TF32(d, a, b0, b1)                                          \
    asm volatile(                                                        \
        "mma.sync.aligned.m16n8k8.row.col.f32.tf32.tf32.f32 "           \
        "{%0,%1,%2,%3}, {%4,%5,%6,%7}, {%8,%9}, {%0,%1,%2,%3};"         \
        : "+f"((d)[0]), "+f"((d)[1]), "+f"((d)[2]), "+f"((d)[3])         \
        : "r"((a)[0]), "r"((a)[1]), "r"((a)[2]), "r"((a)[3]),            \
          "r"(b0), "r"(b1))

// ---------------------------------------------------------------------------
// norms: C_k = sum_e fl(c*c), e ascending (exact chain); float4 loads
// ---------------------------------------------------------------------------
__global__ void k_norms(const float* __restrict__ cb) {
    int idx = blockIdx.x * 64 + threadIdx.x;
    if (idx >= NBOOK * KCB) return;
    const float4* c4 = (const float4*)(cb + (size_t)idx * EDIM);
    float acc = 0.0f;
#pragma unroll 8
    for (int e = 0; e < EDIM / 4; e++) {
        float4 v = __ldg(c4 + e);
        acc = __fadd_rn(acc, __fmul_rn(v.x, v.x));
        acc = __fadd_rn(acc, __fmul_rn(v.y, v.y));
        acc = __fadd_rn(acc, __fmul_rn(v.z, v.z));
        acc = __fadd_rn(acc, __fmul_rn(v.w, v.w));
    }
    g_norms[idx] = acc;
}

// ---------------------------------------------------------------------------
// fused RVQ: one CTA = 128 rows through all 8 books. 512 threads (16 warps).
// Warp grid 4M x 4N; warp tile 32 rows x 32 codes.
// ---------------------------------------------------------------------------
__global__ void __launch_bounds__(TPB, 1)
k_rvq(const float* __restrict__ emb, const float* __restrict__ cb,
      float* __restrict__ out) {
    extern __shared__ float smf[];
    const uint32_t sb = smem_u32(smf);
    const int t = threadIdx.x, lane = t & 31, w = t >> 5;
    const int wm = w & 3, wn = w >> 2;     // 4 M-warps x 4 N-warps
    const int blk = blockIdx.x;
    const int b = blk >> 5;                // batch
    const int hw0 = (blk & 31) << 7;       // hw offset

    float* A     = smf + OFF_A;
    float* sNorm = smf + OFF_NORM;
    float* sA    = smf + OFF_SA;
    unsigned* cellsU = (unsigned*)(smf + OFF_CELLS);
    int*   cnt    = (int*)(smf + OFF_CNT);
    int*   sBest8 = (int*)(smf + OFF_BEST8);
    int*   candk  = (int*)(smf + OFF_CAND);

    // load residual tile (exact): A[i][e] = emb[b][e][hw0+i]
    for (int v = t; v < 128 * 128; v += TPB) {
        int e = v >> 7, i = v & 127;
        A[i * PA + e] = emb[((size_t)(b * 128 + e) << 12) + hw0 + i];
    }
    __syncthreads();

    const int frow = lane >> 2;            // 0..7
    const int fcol = lane & 3;             // 0..3

    for (int book = 0; book < NBOOK; book++) {
        const float* cbg = cb + (size_t)book * KCB * EDIM;

        // book-start: norms, reset cells/cnt, exact A-norms
        for (int v = t; v < KCB; v += TPB) sNorm[v] = g_norms[book * KCB + v];
        for (int v = t; v < NCHUNK * 128; v += TPB) cellsU[v] = 0x7f7fffffu;
        if (t < 128) {
            cnt[t] = 0;
            // A = ||r||^2 exact chain (e ascending, fl(mul) then fl(add))
            float acc = 0.0f;
            const float* ar = &A[t * PA];
            for (int e = 0; e < EDIM; e++)
                acc = __fadd_rn(acc, __fmul_rn(ar[e], ar[e]));
            sA[t] = acc;
        }
        __syncthreads();

        float arg[2][2], premin[2][2];
#pragma unroll
        for (int mt = 0; mt < 2; mt++)
#pragma unroll
            for (int h = 0; h < 2; h++) {
                arg[mt][h] = sA[wm * 32 + mt * 16 + frow + h * 8];
                premin[mt][h] = 3.4e38f;
            }

        // prologue: stage chunk 0 into B0 (per-book, R13 structure)
        for (int v = t; v < CHUNK * 32; v += TPB) {
            int code = v >> 5, s = v & 31;
            cp_async16(sb + (OFF_B0 + code * PB + s * 4) * 4,
                       cbg + (size_t)code * EDIM + s * 4);
        }
        asm volatile("cp.async.commit_group;" ::: "memory");
        asm volatile("cp.async.wait_group 0;" ::: "memory");
        __syncthreads();

        for (int c = 0; c < NCHUNK; c++) {
            const float* Bc = smf + ((c & 1) ? OFF_B1 : OFF_B0);

            // prefetch next chunk into the other buffer.
            // Safe: all warps passed barrier(c-1), which followed MMA(c-1)
            // on the buffer being overwritten.
            if (c + 1 < NCHUNK) {
                int nboff = ((c + 1) & 1) ? OFF_B1 : OFF_B0;
                const float* srcn = cbg + (size_t)(c + 1) * CHUNK * EDIM;
                for (int v = t; v < CHUNK * 32; v += TPB) {
                    int code = v >> 5, s = v & 31;
                    cp_async16(sb + (nboff + code * PB + s * 4) * 4,
                               srcn + (size_t)code * EDIM + s * 4);
                }
                asm volatile("cp.async.commit_group;" ::: "memory");
            }

            // ---- tf32 MMA (truncated fp32 inputs): 2 m16 x 4 n8 x 16 k8 ----
            float d[2][4][4];
#pragma unroll
            for (int mt = 0; mt < 2; mt++)
#pragma unroll
                for (int nt = 0; nt < 4; nt++)
#pragma unroll
                    for (int q = 0; q < 4; q++) d[mt][nt][q] = 0.0f;

#pragma unroll 4
            for (int ks = 0; ks < 16; ks++) {
                int k0 = ks * 8;
                uint32_t a[2][4];
#pragma unroll
                for (int mt = 0; mt < 2; mt++) {
                    int r0 = wm * 32 + mt * 16 + frow;
                    a[mt][0] = __float_as_uint(A[r0 * PA + k0 + fcol]);
                    a[mt][1] = __float_as_uint(A[(r0 + 8) * PA + k0 + fcol]);
                    a[mt][2] = __float_as_uint(A[r0 * PA + k0 + fcol + 4]);
                    a[mt][3] = __float_as_uint(A[(r0 + 8) * PA + k0 + fcol + 4]);
                }
#pragma unroll
                for (int nt = 0; nt < 4; nt++) {
                    int cl = wn * 32 + nt * 8 + frow;
                    uint32_t b0 = __float_as_uint(Bc[cl * PB + k0 + fcol]);
                    uint32_t b1 = __float_as_uint(Bc[cl * PB + k0 + fcol + 4]);
                    MMA_TF32(d[0][nt], a[0], b0, b1);
                    MMA_TF32(d[1][nt], a[1], b0, b1);
                }
            }

            // ---- epilogue: d_app = fma(-2,S,A) + C ----
            int kchunk = c * CHUNK + wn * 32;
#pragma unroll
            for (int mt = 0; mt < 2; mt++)
#pragma unroll
                for (int nt = 0; nt < 4; nt++)
#pragma unroll
                    for (int q = 0; q < 4; q++) {
                        int k = kchunk + nt * 8 + 2 * fcol + (q & 1);
                        d[mt][nt][q] = __fadd_rn(
                            __fmaf_rn(-2.0f, d[mt][nt][q], arg[mt][q >> 1]),
                            sNorm[k]);
                    }

            // per-chunk min into cells[c] ONLY (next chunk writes cells[c+1],
            // so laggards' collect(c) below can never race a writer).
#pragma unroll
            for (int mt = 0; mt < 2; mt++)
#pragma unroll
                for (int h = 0; h < 2; h++) {
                    float lm = 3.4e38f;
#pragma unroll
                    for (int nt = 0; nt < 4; nt++)
                        lm = fminf(lm, fminf(d[mt][nt][h * 2],
                                             d[mt][nt][h * 2 + 1]));
                    int row = wm * 32 + mt * 16 + frow + h * 8;
                    atomicMin(&cellsU[c * 128 + row], __float_as_uint(lm));
                }

            asm volatile("cp.async.wait_group 0;" ::: "memory");
            __syncthreads();   // seals cells[c]; publishes next B buffer

            // ---- collect(c): threshold = FULL prefix-min through chunk c
            // (min of register premin and sealed cells[c]) + EPSM.
            // Bit-identical candidate set to R13's synced rowMin scheme.
#pragma unroll
            for (int mt = 0; mt < 2; mt++)
#pragma unroll
                for (int h = 0; h < 2; h++) {
                    int row = wm * 32 + mt * 16 + frow + h * 8;
                    float pm = fminf(premin[mt][h],
                                     __uint_as_float(cellsU[c * 128 + row]));
                    premin[mt][h] = pm;
                    float thr = pm + EPSM;
#pragma unroll
                    for (int nt = 0; nt < 4; nt++)
#pragma unroll
                        for (int qq = 0; qq < 2; qq++) {
                            if (d[mt][nt][h * 2 + qq] <= thr) {
                                int k = kchunk + nt * 8 + 2 * fcol + qq;
                                int p = atomicAdd(&cnt[row], 1);
                                if (p < CANDMAX)
                                    candk[row * CANDMAX + p] = k;
                            }
                        }
                }
        }
        __syncthreads();   // all collects done before refine reads cnt/candk

        // ---- exact refine: thread t owns row t (chains identical to R1) ----
        if (t < 128) {
            int n = cnt[t];
            float Arow = sA[t];
            float bd = 3.4e38f; int bk = 0x7fffffff;
            const float* ar = &A[t * PA];
            if (n <= CANDMAX) {
                for (int i = 0; i < n; i++) {
                    int k = candk[t * CANDMAX + i];
                    const float* cp = cbg + (size_t)k * EDIM;
                    float dot = 0.0f;
#pragma unroll 8
                    for (int e = 0; e < EDIM; e += 4) {
                        float4 c4 = __ldg((const float4*)(cp + e));
                        dot = __fmaf_rn(ar[e], c4.x, dot);
                        dot = __fmaf_rn(ar[e + 1], c4.y, dot);
                        dot = __fmaf_rn(ar[e + 2], c4.z, dot);
                        dot = __fmaf_rn(ar[e + 3], c4.w, dot);
                    }
                    float dd = __fadd_rn(__fsub_rn(Arow, 2.0f * dot), sNorm[k]);
                    if (dd < bd || (dd == bd && k < bk)) { bd = dd; bk = k; }
                }
            } else {   // safety fallback: exact full scan (deterministic)
                for (int k = 0; k < KCB; k++) {
                    const float* cp = cbg + (size_t)k * EDIM;
                    float dot = 0.0f;
                    for (int e = 0; e < EDIM; e += 4) {
                        float4 c4 = __ldg((const float4*)(cp + e));
                        dot = __fmaf_rn(ar[e], c4.x, dot);
                        dot = __fmaf_rn(ar[e + 1], c4.y, dot);
                        dot = __fmaf_rn(ar[e + 2], c4.z, dot);
                        dot = __fmaf_rn(ar[e + 3], c4.w, dot);
                    }
                    float dd = __fadd_rn(__fsub_rn(Arow, 2.0f * dot), sNorm[k]);
                    if (dd < bd) { bd = dd; bk = k; }
                }
            }
            sBest8[book * 128 + t] = bk;
        }
        __syncthreads();

        // ---- res -= dec (SMEM, exact). Skipped for last book (res dead). ----
        if (book < NBOOK - 1) {
            for (int v = t; v < 128 * 32; v += TPB) {
                int row = v >> 5, e4 = (v & 31) << 2;
                int k = sBest8[book * 128 + row];
                float4 dec = __ldg((const float4*)(cbg + (size_t)k * EDIM + e4));
                float* rp = &A[row * PA + e4];
                rp[0] = __fsub_rn(rp[0], dec.x);
                rp[1] = __fsub_rn(rp[1], dec.y);
                rp[2] = __fsub_rn(rp[2], dec.z);
                rp[3] = __fsub_rn(rp[3], dec.w);
            }
            __syncthreads();
        }
    }
    __syncthreads();

    // ---- quant reconstruction: q = ((dec0+dec1)+...+dec7), exact order ----
    float* Q = smf + OFF_B0;
    for (int v = t; v < 128 * 32; v += TPB) {
        int row = v >> 5, e4 = (v & 31) << 2;
        float4 q = __ldg((const float4*)(
            cb + ((size_t)sBest8[row]) * EDIM + e4));   // book 0
#pragma unroll
        for (int bkk = 1; bkk < NBOOK; bkk++) {
            int k = sBest8[bkk * 128 + row];
            float4 dv = __ldg((const float4*)(
                cb + ((size_t)bkk * KCB + k) * EDIM + e4));
            q.x = __fadd_rn(q.x, dv.x); q.y = __fadd_rn(q.y, dv.y);
            q.z = __fadd_rn(q.z, dv.z); q.w = __fadd_rn(q.w, dv.w);
        }
        *(float4*)&Q[row * PA + e4] = q;
    }
    __syncthreads();

    // ---- output: Q [row][e] (smem) -> out NCHW, warp-tiled transpose ----
    {
        float* ts = smf + OFF_B1 + w * (32 * 33);
        int i0 = (w & 3) * 32, e0 = (w >> 2) * 32;
#pragma unroll 4
        for (int r = 0; r < 32; r++)
            ts[r * 33 + lane] = Q[(i0 + r) * PA + e0 + lane];
        __syncwarp();
#pragma unroll 4
        for (int r = 0; r < 32; r++)
            out[((size_t)(b * 128 + e0 + r) << 12) + hw0 + i0 + lane] =
                ts[lane * 33 + r];
    }
}

// ---------------------------------------------------------------------------
extern "C" void kernel_launch(void* const* d_in, const int* in_sizes, int n_in,
                              void* d_out, int out_size) {
    (void)in_sizes; (void)n_in; (void)out_size;
    const float* emb = (const float*)d_in[0];
    const float* cb  = (const float*)d_in[1];
    float* out = (float*)d_out;

    const int smem_bytes = SM_FLOATS * 4;
    cudaFuncSetAttribute(k_rvq, cudaFuncAttributeMaxDynamicSharedMemorySize,
                         smem_bytes);
    k_norms<<<NBOOK * KCB / 64, 64>>>(cb);
    k_rvq<<<NROWS / 128, TPB, smem_bytes>>>(emb, cb, out);
}